// round 1
// baseline (speedup 1.0000x reference)
#include <cuda_runtime.h>
#include <cstdint>

#define NNODES 100000
#define NEDGES 1600000

// ---------------- device scratch (no allocations allowed) ----------------
__device__ int   g_deg[NNODES];
__device__ int   g_cur[NNODES];
__device__ int   g_off[NNODES + 1];
__device__ int   g_bsum[128];
__device__ int   g_csr[NEDGES];
__device__ float g_agg[(size_t)NNODES * 128];
__device__ float g_h1 [(size_t)NNODES * 128];

// ---------------- packed f32x2 helpers (FFMA2 path) ----------------
__device__ __forceinline__ unsigned long long pack2(float v) {
    unsigned long long r;
    asm("mov.b64 %0, {%1, %1};" : "=l"(r) : "f"(v));
    return r;
}
__device__ __forceinline__ void fma2(unsigned long long& acc,
                                     unsigned long long a,
                                     unsigned long long b) {
    asm("fma.rn.f32x2 %0, %1, %2, %0;" : "+l"(acc) : "l"(a), "l"(b));
}
__device__ __forceinline__ void unpack2(unsigned long long v, float& lo, float& hi) {
    asm("mov.b64 {%0, %1}, %2;" : "=f"(lo), "=f"(hi) : "l"(v));
}

// ---------------- CSR build ----------------
__global__ void k_init(int n) {
    int i = blockIdx.x * blockDim.x + threadIdx.x;
    if (i < n) { g_deg[i] = 0; g_cur[i] = 0; }
}

__global__ void k_count(const int* __restrict__ dst, int e) {
    int i = blockIdx.x * blockDim.x + threadIdx.x;
    if (i < e) atomicAdd(&g_deg[dst[i]], 1);
}

// exclusive scan of g_deg into g_off: 3-kernel two-level scan
__global__ void k_scan1(int n) {
    __shared__ int sh[1024];
    int t = threadIdx.x;
    int i = blockIdx.x * 1024 + t;
    int v = (i < n) ? g_deg[i] : 0;
    sh[t] = v;
    __syncthreads();
#pragma unroll
    for (int o = 1; o < 1024; o <<= 1) {
        int x = (t >= o) ? sh[t - o] : 0;
        __syncthreads();
        sh[t] += x;
        __syncthreads();
    }
    if (i < n) g_off[i] = sh[t] - v;   // exclusive
    if (t == 1023) g_bsum[blockIdx.x] = sh[1023];
}

__global__ void k_scan2(int nb, int n) {
    __shared__ int sh[128];
    int t = threadIdx.x;
    int v = (t < nb) ? g_bsum[t] : 0;
    sh[t] = v;
    __syncthreads();
#pragma unroll
    for (int o = 1; o < 128; o <<= 1) {
        int x = (t >= o) ? sh[t - o] : 0;
        __syncthreads();
        sh[t] += x;
        __syncthreads();
    }
    g_bsum[t] = sh[t] - v;             // exclusive block offsets
    if (t == 127) g_off[n] = sh[127];  // total = E
}

__global__ void k_scan3(int n) {
    int i = blockIdx.x * blockDim.x + threadIdx.x;
    if (i < n) g_off[i] += g_bsum[i >> 10];
}

__global__ void k_fill(const int* __restrict__ src, const int* __restrict__ dst, int e) {
    int i = blockIdx.x * blockDim.x + threadIdx.x;
    if (i < e) {
        int d = dst[i];
        int p = atomicAdd(&g_cur[d], 1);
        g_csr[g_off[d] + p] = src[i];
    }
}

// ---------------- mean aggregation: one warp per destination node ----------------
__global__ void k_agg(const float* __restrict__ xin, int n, int use_h1) {
    const float* __restrict__ x = use_h1 ? (const float*)g_h1 : xin;
    int w    = (blockIdx.x * blockDim.x + threadIdx.x) >> 5;
    int lane = threadIdx.x & 31;
    if (w >= n) return;
    int b  = g_off[w];
    int e2 = g_off[w + 1];
    float4 acc = make_float4(0.f, 0.f, 0.f, 0.f);
#pragma unroll 4
    for (int i = b; i < e2; i++) {
        int s = g_csr[i];
        float4 v = ((const float4*)(x + (size_t)s * 128))[lane];
        acc.x += v.x; acc.y += v.y; acc.z += v.z; acc.w += v.w;
    }
    float inv = 1.0f / (float)max(e2 - b, 1);
    float4 r = make_float4(acc.x * inv, acc.y * inv, acc.z * inv, acc.w * inv);
    ((float4*)(g_agg + (size_t)w * 128))[lane] = r;
}

// ---------------- GEMM1: h1 = relu(x @ W1s + agg @ W1n + b1) ----------------
// block tile 128x128, thread tile 8 rows x 8 cols (as 4 f32x2 pairs, FFMA2)
__global__ __launch_bounds__(256) void k_gemm1(
    const float* __restrict__ A0,
    const float* __restrict__ W0, const float* __restrict__ W1,
    const float* __restrict__ bias, int n)
{
    __shared__ __align__(16) float As[16][128];
    __shared__ __align__(16) float Ws[16][128];
    const int tid = threadIdx.x;
    const int tx = tid & 15;   // col groups: [tx*4, tx*4+4) and [64+tx*4, 64+tx*4+4)
    const int ty = tid >> 4;   // rows [ty*8, ty*8+8)
    const int rowBase = blockIdx.x * 128;

    unsigned long long acc[8][4];
#pragma unroll
    for (int i = 0; i < 8; i++)
#pragma unroll
        for (int j = 0; j < 4; j++) acc[i][j] = 0ULL;

    for (int m = 0; m < 2; m++) {
        const float* __restrict__ A = (m == 0) ? A0 : (const float*)g_agg;
        const float* __restrict__ W = (m == 0) ? W0 : W1;
#pragma unroll 1
        for (int s = 0; s < 8; s++) {
            const int k0 = s * 16;
#pragma unroll
            for (int it = 0; it < 2; it++) {
                int idx  = tid + it * 256;
                int c4   = idx >> 7;        // 0..3
                int row  = idx & 127;
                int grow = rowBase + row;
                float4 v = make_float4(0.f, 0.f, 0.f, 0.f);
                if (grow < n)
                    v = *(const float4*)(A + (size_t)grow * 128 + k0 + c4 * 4);
                As[c4 * 4 + 0][row] = v.x;
                As[c4 * 4 + 1][row] = v.y;
                As[c4 * 4 + 2][row] = v.z;
                As[c4 * 4 + 3][row] = v.w;
                int kr = idx >> 5;          // 0..15
                int wc = idx & 31;          // 0..31
                float4 wv = *(const float4*)(W + (size_t)(k0 + kr) * 128 + wc * 4);
                *(float4*)&Ws[kr][wc * 4] = wv;
            }
            __syncthreads();
#pragma unroll
            for (int k = 0; k < 16; k++) {
                float a[8];
                *(float4*)&a[0] = *(const float4*)&As[k][ty * 8];
                *(float4*)&a[4] = *(const float4*)&As[k][ty * 8 + 4];
                ulonglong2 q0 = *(const ulonglong2*)&Ws[k][tx * 4];
                ulonglong2 q1 = *(const ulonglong2*)&Ws[k][64 + tx * 4];
#pragma unroll
                for (int i = 0; i < 8; i++) {
                    unsigned long long ap = pack2(a[i]);
                    fma2(acc[i][0], ap, q0.x);
                    fma2(acc[i][1], ap, q0.y);
                    fma2(acc[i][2], ap, q1.x);
                    fma2(acc[i][3], ap, q1.y);
                }
            }
            __syncthreads();
        }
    }

    float4 bia0 = *(const float4*)(bias + tx * 4);
    float4 bia1 = *(const float4*)(bias + 64 + tx * 4);
#pragma unroll
    for (int i = 0; i < 8; i++) {
        int row = rowBase + ty * 8 + i;
        if (row < n) {
            float4 r0, r1;
            unpack2(acc[i][0], r0.x, r0.y);
            unpack2(acc[i][1], r0.z, r0.w);
            unpack2(acc[i][2], r1.x, r1.y);
            unpack2(acc[i][3], r1.z, r1.w);
            r0.x = fmaxf(r0.x + bia0.x, 0.f);
            r0.y = fmaxf(r0.y + bia0.y, 0.f);
            r0.z = fmaxf(r0.z + bia0.z, 0.f);
            r0.w = fmaxf(r0.w + bia0.w, 0.f);
            r1.x = fmaxf(r1.x + bia1.x, 0.f);
            r1.y = fmaxf(r1.y + bia1.y, 0.f);
            r1.z = fmaxf(r1.z + bia1.z, 0.f);
            r1.w = fmaxf(r1.w + bia1.w, 0.f);
            *(float4*)(g_h1 + (size_t)row * 128 + tx * 4)      = r0;
            *(float4*)(g_h1 + (size_t)row * 128 + 64 + tx * 4) = r1;
        }
    }
}

// ---------------- GEMM2: out = h1 @ W2s + agg2 @ W2n + b2 ----------------
// block tile 128 rows x 40 cols; thread tile 4 rows x 5 cols; full W in smem
__global__ __launch_bounds__(256) void k_gemm2(
    const float* __restrict__ W0, const float* __restrict__ W1,
    const float* __restrict__ bias, float* __restrict__ out, int n)
{
    __shared__ __align__(16) float Wall[256 * 40];  // 40 KB: rows 0..127 = W2s, 128..255 = W2n
    __shared__ __align__(16) float As[16][128];     // 8 KB
    const int tid = threadIdx.x;
    const int tx = tid & 7;    // cols [tx*5, tx*5+5)
    const int ty = tid >> 3;   // rows [ty*4, ty*4+4)
    const int rowBase = blockIdx.x * 128;

    for (int idx = tid; idx < 256 * 40; idx += 256)
        Wall[idx] = (idx < 128 * 40) ? W0[idx] : W1[idx - 128 * 40];

    float acc[4][5];
#pragma unroll
    for (int i = 0; i < 4; i++)
#pragma unroll
        for (int j = 0; j < 5; j++) acc[i][j] = 0.f;

    for (int m = 0; m < 2; m++) {
        const float* __restrict__ A = (m == 0) ? (const float*)g_h1 : (const float*)g_agg;
#pragma unroll 1
        for (int s = 0; s < 8; s++) {
            const int k0 = s * 16;
#pragma unroll
            for (int it = 0; it < 2; it++) {
                int idx  = tid + it * 256;
                int c4   = idx >> 7;
                int row  = idx & 127;
                int grow = rowBase + row;
                float4 v = make_float4(0.f, 0.f, 0.f, 0.f);
                if (grow < n)
                    v = *(const float4*)(A + (size_t)grow * 128 + k0 + c4 * 4);
                As[c4 * 4 + 0][row] = v.x;
                As[c4 * 4 + 1][row] = v.y;
                As[c4 * 4 + 2][row] = v.z;
                As[c4 * 4 + 3][row] = v.w;
            }
            __syncthreads();
#pragma unroll
            for (int k = 0; k < 16; k++) {
                float a[4];
                *(float4*)&a[0] = *(const float4*)&As[k][ty * 4];
                const float* wrow = &Wall[(size_t)(m * 128 + k0 + k) * 40 + tx * 5];
                float b0 = wrow[0], b1 = wrow[1], b2 = wrow[2], b3 = wrow[3], b4 = wrow[4];
#pragma unroll
                for (int i = 0; i < 4; i++) {
                    acc[i][0] += a[i] * b0;
                    acc[i][1] += a[i] * b1;
                    acc[i][2] += a[i] * b2;
                    acc[i][3] += a[i] * b3;
                    acc[i][4] += a[i] * b4;
                }
            }
            __syncthreads();
        }
    }

    float bb[5];
#pragma unroll
    for (int j = 0; j < 5; j++) bb[j] = bias[tx * 5 + j];
#pragma unroll
    for (int i = 0; i < 4; i++) {
        int row = rowBase + ty * 4 + i;
        if (row < n) {
#pragma unroll
            for (int j = 0; j < 5; j++)
                out[(size_t)row * 40 + tx * 5 + j] = acc[i][j] + bb[j];
        }
    }
}

// ---------------- launch ----------------
extern "C" void kernel_launch(void* const* d_in, const int* in_sizes, int n_in,
                              void* d_out, int out_size) {
    const float* x   = (const float*)d_in[0];
    const int*   src = (const int*)  d_in[1];
    const int*   dst = (const int*)  d_in[2];
    const float* W1s = (const float*)d_in[3];
    const float* W1n = (const float*)d_in[4];
    const float* b1  = (const float*)d_in[5];
    const float* W2s = (const float*)d_in[6];
    const float* W2n = (const float*)d_in[7];
    const float* b2  = (const float*)d_in[8];
    float* out = (float*)d_out;

    const int E = in_sizes[1];
    const int N = in_sizes[0] / 128;
    const int nb = (N + 1023) / 1024;

    k_init <<<(N + 255) / 256, 256>>>(N);
    k_count<<<(E + 255) / 256, 256>>>(dst, E);
    k_scan1<<<nb, 1024>>>(N);
    k_scan2<<<1, 128>>>(nb, N);
    k_scan3<<<(N + 255) / 256, 256>>>(N);
    k_fill <<<(E + 255) / 256, 256>>>(src, dst, E);

    k_agg  <<<(N + 7) / 8, 256>>>(x, N, 0);                 // agg1 = mean(x)
    k_gemm1<<<(N + 127) / 128, 256>>>(x, W1s, W1n, b1, N);  // h1
    k_agg  <<<(N + 7) / 8, 256>>>(x, N, 1);                 // agg2 = mean(h1)
    k_gemm2<<<(N + 127) / 128, 256>>>(W2s, W2n, b2, out, N);
}

// round 3
// speedup vs baseline: 1.0488x; 1.0488x over previous
#include <cuda_runtime.h>
#include <cuda_fp16.h>
#include <cstdint>

#define NNODES 100000
#define NEDGES 1600000

// ---------------- device scratch (no allocations allowed) ----------------
__device__ int    g_deg[NNODES];
__device__ int    g_cur[NNODES];
__device__ int    g_off[NNODES + 1];
__device__ int    g_bsum[128];
__device__ int    g_csr[NEDGES];
__device__ __half g_xh[(size_t)NNODES * 128];   // fp16 copy of input features
__device__ float  g_agg[(size_t)NNODES * 128];  // mean-aggregated x (fp32)
__device__ float  g_h1 [(size_t)NNODES * 128];  // layer-1 output
__device__ float  g_s  [(size_t)NNODES * 40];   // h1 @ W2_self + b2
__device__ __half g_t  [(size_t)NNODES * 64];   // h1 @ W2_neigh (fp16, padded row=64)

// ---------------- packed f32x2 helpers (FFMA2 path) ----------------
__device__ __forceinline__ unsigned long long pack2(float v) {
    unsigned long long r;
    asm("mov.b64 %0, {%1, %1};" : "=l"(r) : "f"(v));
    return r;
}
__device__ __forceinline__ void fma2(unsigned long long& acc,
                                     unsigned long long a,
                                     unsigned long long b) {
    asm("fma.rn.f32x2 %0, %1, %2, %0;" : "+l"(acc) : "l"(a), "l"(b));
}
__device__ __forceinline__ void unpack2(unsigned long long v, float& lo, float& hi) {
    asm("mov.b64 {%0, %1}, %2;" : "=f"(lo), "=f"(hi) : "l"(v));
}

// ---------------- prep: zero degree counters + convert x to fp16 ----------------
__global__ void k_prep(const float* __restrict__ x, int n) {
    int i = blockIdx.x * blockDim.x + threadIdx.x;
    if (i < n) g_deg[i] = 0;
    if (i < n * 64) {
        float2 v = ((const float2*)x)[i];
        ((__half2*)g_xh)[i] = __float22half2_rn(v);
    }
}

__global__ void k_count(const int* __restrict__ dst, int e) {
    int i = blockIdx.x * blockDim.x + threadIdx.x;
    if (i < e) atomicAdd(&g_deg[dst[i]], 1);
}

// exclusive scan of g_deg into g_off: 3-kernel two-level scan
__global__ void k_scan1(int n) {
    __shared__ int sh[1024];
    int t = threadIdx.x;
    int i = blockIdx.x * 1024 + t;
    int v = (i < n) ? g_deg[i] : 0;
    sh[t] = v;
    __syncthreads();
#pragma unroll
    for (int o = 1; o < 1024; o <<= 1) {
        int x = (t >= o) ? sh[t - o] : 0;
        __syncthreads();
        sh[t] += x;
        __syncthreads();
    }
    if (i < n) g_off[i] = sh[t] - v;   // exclusive
    if (t == 1023) g_bsum[blockIdx.x] = sh[1023];
}

__global__ void k_scan2(int nb, int n) {
    __shared__ int sh[128];
    int t = threadIdx.x;
    int v = (t < nb) ? g_bsum[t] : 0;
    sh[t] = v;
    __syncthreads();
#pragma unroll
    for (int o = 1; o < 128; o <<= 1) {
        int x = (t >= o) ? sh[t - o] : 0;
        __syncthreads();
        sh[t] += x;
        __syncthreads();
    }
    g_bsum[t] = sh[t] - v;             // exclusive block offsets
    if (t == 127) g_off[n] = sh[127];  // total = E
}

__global__ void k_scan3(int n) {
    int i = blockIdx.x * blockDim.x + threadIdx.x;
    if (i < n) { g_off[i] += g_bsum[i >> 10]; g_cur[i] = 0; }
}

__global__ void k_fill(const int* __restrict__ src, const int* __restrict__ dst, int e) {
    int i = blockIdx.x * blockDim.x + threadIdx.x;
    if (i < e) {
        int d = dst[i];
        int p = atomicAdd(&g_cur[d], 1);
        g_csr[g_off[d] + p] = src[i];
    }
}

// ---------------- mean aggregation of fp16 features: one warp per node ----------------
// row = 128 halves = 32 uint2; each lane owns one uint2 (4 halves)
__global__ void k_aggh(int n) {
    int w    = (blockIdx.x * blockDim.x + threadIdx.x) >> 5;
    int lane = threadIdx.x & 31;
    if (w >= n) return;
    int b  = g_off[w];
    int e2 = g_off[w + 1];
    float2 a0 = make_float2(0.f, 0.f), a1 = make_float2(0.f, 0.f);
    const uint2* __restrict__ base = (const uint2*)g_xh;
#pragma unroll 4
    for (int i = b; i < e2; i++) {
        int s = g_csr[i];
        uint2 raw = base[(size_t)s * 32 + lane];   // FIXED: 32 uint2 per row
        float2 f0 = __half22float2(*(__half2*)&raw.x);
        float2 f1 = __half22float2(*(__half2*)&raw.y);
        a0.x += f0.x; a0.y += f0.y; a1.x += f1.x; a1.y += f1.y;
    }
    float inv = 1.0f / (float)max(e2 - b, 1);
    float4 r = make_float4(a0.x * inv, a0.y * inv, a1.x * inv, a1.y * inv);
    ((float4*)(g_agg + (size_t)w * 128))[lane] = r;
}

// ---------------- GEMM1: h1 = relu(x @ W1s + agg @ W1n + b1) ----------------
__global__ __launch_bounds__(256) void k_gemm1(
    const float* __restrict__ A0,
    const float* __restrict__ W0, const float* __restrict__ W1,
    const float* __restrict__ bias, int n)
{
    __shared__ __align__(16) float As[16][128];
    __shared__ __align__(16) float Ws[16][128];
    const int tid = threadIdx.x;
    const int tx = tid & 15;
    const int ty = tid >> 4;
    const int rowBase = blockIdx.x * 128;

    unsigned long long acc[8][4];
#pragma unroll
    for (int i = 0; i < 8; i++)
#pragma unroll
        for (int j = 0; j < 4; j++) acc[i][j] = 0ULL;

    for (int m = 0; m < 2; m++) {
        const float* __restrict__ A = (m == 0) ? A0 : (const float*)g_agg;
        const float* __restrict__ W = (m == 0) ? W0 : W1;
#pragma unroll 1
        for (int s = 0; s < 8; s++) {
            const int k0 = s * 16;
#pragma unroll
            for (int it = 0; it < 2; it++) {
                int idx  = tid + it * 256;
                int c4   = idx >> 7;
                int row  = idx & 127;
                int grow = rowBase + row;
                float4 v = make_float4(0.f, 0.f, 0.f, 0.f);
                if (grow < n)
                    v = *(const float4*)(A + (size_t)grow * 128 + k0 + c4 * 4);
                As[c4 * 4 + 0][row] = v.x;
                As[c4 * 4 + 1][row] = v.y;
                As[c4 * 4 + 2][row] = v.z;
                As[c4 * 4 + 3][row] = v.w;
                int kr = idx >> 5;
                int wc = idx & 31;
                float4 wv = *(const float4*)(W + (size_t)(k0 + kr) * 128 + wc * 4);
                *(float4*)&Ws[kr][wc * 4] = wv;
            }
            __syncthreads();
#pragma unroll
            for (int k = 0; k < 16; k++) {
                float a[8];
                *(float4*)&a[0] = *(const float4*)&As[k][ty * 8];
                *(float4*)&a[4] = *(const float4*)&As[k][ty * 8 + 4];
                ulonglong2 q0 = *(const ulonglong2*)&Ws[k][tx * 4];
                ulonglong2 q1 = *(const ulonglong2*)&Ws[k][64 + tx * 4];
#pragma unroll
                for (int i = 0; i < 8; i++) {
                    unsigned long long ap = pack2(a[i]);
                    fma2(acc[i][0], ap, q0.x);
                    fma2(acc[i][1], ap, q0.y);
                    fma2(acc[i][2], ap, q1.x);
                    fma2(acc[i][3], ap, q1.y);
                }
            }
            __syncthreads();
        }
    }

    float4 bia0 = *(const float4*)(bias + tx * 4);
    float4 bia1 = *(const float4*)(bias + 64 + tx * 4);
#pragma unroll
    for (int i = 0; i < 8; i++) {
        int row = rowBase + ty * 8 + i;
        if (row < n) {
            float4 r0, r1;
            unpack2(acc[i][0], r0.x, r0.y);
            unpack2(acc[i][1], r0.z, r0.w);
            unpack2(acc[i][2], r1.x, r1.y);
            unpack2(acc[i][3], r1.z, r1.w);
            r0.x = fmaxf(r0.x + bia0.x, 0.f);
            r0.y = fmaxf(r0.y + bia0.y, 0.f);
            r0.z = fmaxf(r0.z + bia0.z, 0.f);
            r0.w = fmaxf(r0.w + bia0.w, 0.f);
            r1.x = fmaxf(r1.x + bia1.x, 0.f);
            r1.y = fmaxf(r1.y + bia1.y, 0.f);
            r1.z = fmaxf(r1.z + bia1.z, 0.f);
            r1.w = fmaxf(r1.w + bia1.w, 0.f);
            *(float4*)(g_h1 + (size_t)row * 128 + tx * 4)      = r0;
            *(float4*)(g_h1 + (size_t)row * 128 + 64 + tx * 4) = r1;
        }
    }
}

// ---------------- GEMM2a: s = h1 @ W2s + b2 (fp32), t = h1 @ W2n (fp16) ----------------
// block: 128 rows x 80 cols (cols 0..39 = self, 40..79 = neigh); thread tile 8x5
__global__ __launch_bounds__(256) void k_gemm2a(
    const float* __restrict__ W0, const float* __restrict__ W1,
    const float* __restrict__ bias, int n)
{
    __shared__ __align__(16) float Wsh[128 * 80];   // 40 KB
    __shared__ __align__(16) float As[16][128];     // 8 KB
    const int tid = threadIdx.x;
    const int tx = tid & 15;   // col group: 5 cols at tx*5
    const int ty = tid >> 4;   // rows ty*8 .. +8
    const int rowBase = blockIdx.x * 128;

    for (int idx = tid; idx < 128 * 80; idx += 256) {
        int k = idx / 80, c = idx - k * 80;
        Wsh[idx] = (c < 40) ? W0[k * 40 + c] : W1[k * 40 + (c - 40)];
    }

    float acc[8][5];
#pragma unroll
    for (int i = 0; i < 8; i++)
#pragma unroll
        for (int j = 0; j < 5; j++) acc[i][j] = 0.f;

#pragma unroll 1
    for (int s = 0; s < 8; s++) {
        const int k0 = s * 16;
#pragma unroll
        for (int it = 0; it < 2; it++) {
            int idx  = tid + it * 256;
            int c4   = idx >> 7;
            int row  = idx & 127;
            int grow = rowBase + row;
            float4 v = make_float4(0.f, 0.f, 0.f, 0.f);
            if (grow < n)
                v = *(const float4*)(g_h1 + (size_t)grow * 128 + k0 + c4 * 4);
            As[c4 * 4 + 0][row] = v.x;
            As[c4 * 4 + 1][row] = v.y;
            As[c4 * 4 + 2][row] = v.z;
            As[c4 * 4 + 3][row] = v.w;
        }
        __syncthreads();
#pragma unroll
        for (int k = 0; k < 16; k++) {
            float a[8];
            *(float4*)&a[0] = *(const float4*)&As[k][ty * 8];
            *(float4*)&a[4] = *(const float4*)&As[k][ty * 8 + 4];
            const float* wrow = &Wsh[(k0 + k) * 80 + tx * 5];
            float b0 = wrow[0], b1 = wrow[1], b2 = wrow[2], b3 = wrow[3], b4 = wrow[4];
#pragma unroll
            for (int i = 0; i < 8; i++) {
                acc[i][0] += a[i] * b0;
                acc[i][1] += a[i] * b1;
                acc[i][2] += a[i] * b2;
                acc[i][3] += a[i] * b3;
                acc[i][4] += a[i] * b4;
            }
        }
        __syncthreads();
    }

    if (tx < 8) {  // self half -> g_s (fp32) + bias
        float bb[5];
#pragma unroll
        for (int j = 0; j < 5; j++) bb[j] = bias[tx * 5 + j];
#pragma unroll
        for (int i = 0; i < 8; i++) {
            int row = rowBase + ty * 8 + i;
            if (row < n) {
#pragma unroll
                for (int j = 0; j < 5; j++)
                    g_s[(size_t)row * 40 + tx * 5 + j] = acc[i][j] + bb[j];
            }
        }
    } else {       // neigh half -> g_t (fp16, padded stride 64)
        int c0 = (tx - 8) * 5;
#pragma unroll
        for (int i = 0; i < 8; i++) {
            int row = rowBase + ty * 8 + i;
            if (row < n) {
#pragma unroll
                for (int j = 0; j < 5; j++)
                    g_t[(size_t)row * 64 + c0 + j] = __float2half(acc[i][j]);
            }
        }
    }
}

// ---------------- final: out = s + mean_agg(t) ----------------
__global__ void k_agg40(float* __restrict__ out, int n) {
    int w    = (blockIdx.x * blockDim.x + threadIdx.x) >> 5;
    int lane = threadIdx.x & 31;
    if (w >= n || lane >= 20) return;
    int b  = g_off[w];
    int e2 = g_off[w + 1];
    float2 acc = make_float2(0.f, 0.f);
    const __half2* __restrict__ base = (const __half2*)g_t;
#pragma unroll 4
    for (int i = b; i < e2; i++) {
        int s = g_csr[i];
        float2 f = __half22float2(base[(size_t)s * 32 + lane]);
        acc.x += f.x; acc.y += f.y;
    }
    float inv = 1.0f / (float)max(e2 - b, 1);
    float2 sv = ((const float2*)(g_s + (size_t)w * 40))[lane];
    float2 r = make_float2(sv.x + acc.x * inv, sv.y + acc.y * inv);
    ((float2*)(out + (size_t)w * 40))[lane] = r;
}

// ---------------- launch ----------------
extern "C" void kernel_launch(void* const* d_in, const int* in_sizes, int n_in,
                              void* d_out, int out_size) {
    const float* x   = (const float*)d_in[0];
    const int*   src = (const int*)  d_in[1];
    const int*   dst = (const int*)  d_in[2];
    const float* W1s = (const float*)d_in[3];
    const float* W1n = (const float*)d_in[4];
    const float* b1  = (const float*)d_in[5];
    const float* W2s = (const float*)d_in[6];
    const float* W2n = (const float*)d_in[7];
    const float* b2  = (const float*)d_in[8];
    float* out = (float*)d_out;

    const int E = in_sizes[1];
    const int N = in_sizes[0] / 128;
    const int nb = (N + 1023) / 1024;

    k_prep <<<(N * 64 + 255) / 256, 256>>>(x, N);
    k_count<<<(E + 255) / 256, 256>>>(dst, E);
    k_scan1<<<nb, 1024>>>(N);
    k_scan2<<<1, 128>>>(nb, N);
    k_scan3<<<(N + 255) / 256, 256>>>(N);
    k_fill <<<(E + 255) / 256, 256>>>(src, dst, E);

    k_aggh  <<<(N + 7) / 8, 256>>>(N);                        // agg1 = mean(x) via fp16
    k_gemm1 <<<(N + 127) / 128, 256>>>(x, W1s, W1n, b1, N);   // h1
    k_gemm2a<<<(N + 127) / 128, 256>>>(W2s, W2n, b2, N);      // s, t
    k_agg40 <<<(N + 7) / 8, 256>>>(out, N);                   // out = s + mean(t)
}

// round 5
// speedup vs baseline: 1.6508x; 1.5740x over previous
#include <cuda_runtime.h>
#include <cuda_fp16.h>
#include <cstdint>

#define NNODES 100000
#define NEDGES 1600000

// ---------------- device scratch ----------------
__device__ int    g_deg[NNODES];
__device__ int    g_cur[NNODES];
__device__ int    g_off[NNODES + 1];
__device__ int    g_bsum[128];
__device__ int    g_csr[NEDGES];
__device__ __half g_a1[(size_t)NNODES * 256];   // [x fp16 (0..127) | agg fp16 (128..255)]
__device__ __half g_w1t[128 * 256];             // W1 concat, transposed: [n][k]
__device__ __half g_w2t[80 * 128];              // W2 concat, transposed: [n][k]
__device__ __half g_h1h[(size_t)NNODES * 128];  // relu layer-1 output, fp16
__device__ float  g_s [(size_t)NNODES * 40];    // h1 @ W2_self + b2
__device__ __half g_t [(size_t)NNODES * 64];    // h1 @ W2_neigh (fp16, stride 64)

// ---------------- baseline-PTX MMA helpers ----------------
__device__ __forceinline__ uint32_t smem_to_u32(const void* p) {
    uint32_t a;
    asm("{ .reg .u64 t; cvta.to.shared.u64 t, %1; cvt.u32.u64 %0, t; }" : "=r"(a) : "l"(p));
    return a;
}
__device__ __forceinline__ void ldsm4(uint32_t* r, uint32_t addr) {
    asm volatile("ldmatrix.sync.aligned.m8n8.x4.shared.b16 {%0,%1,%2,%3}, [%4];"
        : "=r"(r[0]), "=r"(r[1]), "=r"(r[2]), "=r"(r[3]) : "r"(addr));
}
__device__ __forceinline__ void mma16816(float* d, const uint32_t* a, const uint32_t* b) {
    asm volatile("mma.sync.aligned.m16n8k16.row.col.f32.f16.f16.f32 "
        "{%0,%1,%2,%3}, {%4,%5,%6,%7}, {%8,%9}, {%0,%1,%2,%3};"
        : "+f"(d[0]), "+f"(d[1]), "+f"(d[2]), "+f"(d[3])
        : "r"(a[0]), "r"(a[1]), "r"(a[2]), "r"(a[3]), "r"(b[0]), "r"(b[1]));
}

// ---------------- prep ----------------
__global__ void k_prep(const float* __restrict__ x, int n) {
    int i = blockIdx.x * blockDim.x + threadIdx.x;
    if (i < n) g_deg[i] = 0;
    if (i < n * 64) {
        int row = i >> 6, c2 = i & 63;
        float2 v = ((const float2*)x)[i];
        ((__half2*)g_a1)[(size_t)row * 128 + c2] = __float22half2_rn(v);
    }
}

__global__ void k_prepw(const float* __restrict__ W1s, const float* __restrict__ W1n,
                        const float* __restrict__ W2s, const float* __restrict__ W2n) {
    int i = blockIdx.x * blockDim.x + threadIdx.x;
    if (i < 128 * 256) {
        int nn = i >> 8, k = i & 255;
        float v = (k < 128) ? W1s[k * 128 + nn] : W1n[(k - 128) * 128 + nn];
        g_w1t[nn * 256 + k] = __float2half(v);
    } else if (i < 128 * 256 + 80 * 128) {
        int j = i - 128 * 256;
        int nn = j >> 7, k = j & 127;
        float v = (nn < 40) ? W2s[k * 40 + nn] : W2n[k * 40 + (nn - 40)];
        g_w2t[nn * 128 + k] = __float2half(v);
    }
}

// ---------------- CSR build ----------------
__global__ void k_count(const int* __restrict__ dst, int e) {
    int i = blockIdx.x * blockDim.x + threadIdx.x;
    if (i < e) atomicAdd(&g_deg[dst[i]], 1);
}

__global__ void k_scan1(int n) {
    __shared__ int sh[1024];
    int t = threadIdx.x;
    int i = blockIdx.x * 1024 + t;
    int v = (i < n) ? g_deg[i] : 0;
    sh[t] = v;
    __syncthreads();
#pragma unroll
    for (int o = 1; o < 1024; o <<= 1) {
        int x = (t >= o) ? sh[t - o] : 0;
        __syncthreads();
        sh[t] += x;
        __syncthreads();
    }
    if (i < n) g_off[i] = sh[t] - v;
    if (t == 1023) g_bsum[blockIdx.x] = sh[1023];
}

__global__ void k_scan2(int nb, int n) {
    __shared__ int sh[128];
    int t = threadIdx.x;
    int v = (t < nb) ? g_bsum[t] : 0;
    sh[t] = v;
    __syncthreads();
#pragma unroll
    for (int o = 1; o < 128; o <<= 1) {
        int x = (t >= o) ? sh[t - o] : 0;
        __syncthreads();
        sh[t] += x;
        __syncthreads();
    }
    g_bsum[t] = sh[t] - v;
    if (t == 127) g_off[n] = sh[127];
}

__global__ void k_scan3(int n) {
    int i = blockIdx.x * blockDim.x + threadIdx.x;
    if (i < n) { g_off[i] += g_bsum[i >> 10]; g_cur[i] = 0; }
}

__global__ void k_fill(const int* __restrict__ src, const int* __restrict__ dst, int e) {
    int i = blockIdx.x * blockDim.x + threadIdx.x;
    if (i < e) {
        int d = dst[i];
        int p = atomicAdd(&g_cur[d], 1);
        g_csr[g_off[d] + p] = src[i];
    }
}

// ---------------- mean aggregation of fp16 x into g_a1 cols 128..255 ----------------
__global__ void k_aggh(int n) {
    int w    = (blockIdx.x * blockDim.x + threadIdx.x) >> 5;
    int lane = threadIdx.x & 31;
    if (w >= n) return;
    int b  = g_off[w];
    int e2 = g_off[w + 1];
    float2 a0 = make_float2(0.f, 0.f), a1 = make_float2(0.f, 0.f);
    const uint2* __restrict__ base = (const uint2*)g_a1;   // row = 64 uint2
#pragma unroll 4
    for (int i = b; i < e2; i++) {
        int s = g_csr[i];
        uint2 raw = base[(size_t)s * 64 + lane];           // x-part (first 32 uint2)
        float2 f0 = __half22float2(*(__half2*)&raw.x);
        float2 f1 = __half22float2(*(__half2*)&raw.y);
        a0.x += f0.x; a0.y += f0.y; a1.x += f1.x; a1.y += f1.y;
    }
    float inv = 1.0f / (float)max(e2 - b, 1);
    __half2 h0 = __floats2half2_rn(a0.x * inv, a0.y * inv);
    __half2 h1 = __floats2half2_rn(a1.x * inv, a1.y * inv);
    uint2 o;
    o.x = *(uint32_t*)&h0; o.y = *(uint32_t*)&h1;
    ((uint2*)g_a1)[(size_t)w * 64 + 32 + lane] = o;
}

// ---------------- GEMM1 (HMMA): h1 = relu([x|agg] @ W1t^T + b1), fp16 out ----------------
// block 128x128, K=256. 8 warps: 2(m) x 4(n); warp tile 64x32.
__global__ __launch_bounds__(256, 1) void k_gemm1_mma(const float* __restrict__ bias, int n) {
    extern __shared__ __align__(16) char smem[];   // A 64KB | B 64KB
    uint4* sA4 = (uint4*)smem;
    uint4* sB4 = (uint4*)(smem + 65536);
    const int tid = threadIdx.x;
    const int rowBase = blockIdx.x * 128;

    const uint4* a4 = (const uint4*)g_a1;
    for (int i = tid; i < 4096; i += 256) {
        int r = i >> 5, c = i & 31;
        uint4 v = make_uint4(0u, 0u, 0u, 0u);
        int gr = rowBase + r;
        if (gr < n) v = a4[(size_t)gr * 32 + c];
        sA4[r * 32 + (c ^ (r & 7))] = v;
    }
    const uint4* b4 = (const uint4*)g_w1t;
    for (int i = tid; i < 4096; i += 256) {
        int r = i >> 5, c = i & 31;
        sB4[r * 32 + (c ^ (r & 7))] = b4[r * 32 + c];
    }
    __syncthreads();

    const int wid = tid >> 5, lane = tid & 31;
    const int wm = wid >> 2, wn = wid & 3;
    const uint32_t sAb = smem_to_u32(sA4), sBb = smem_to_u32(sB4);

    float acc[4][4][4];
#pragma unroll
    for (int mt = 0; mt < 4; mt++)
#pragma unroll
        for (int nt = 0; nt < 4; nt++)
#pragma unroll
            for (int j = 0; j < 4; j++) acc[mt][nt][j] = 0.f;

    const int lr = lane & 7;
    const int lA_rhi = (lane >> 3) & 1, lA_chi = lane >> 4;   // A: +8 row sel, +k8 chunk sel
    const int lB_rhi = lane >> 4, lB_chi = (lane >> 3) & 1;   // B: +8 row sel, +k8 chunk sel

#pragma unroll 4
    for (int ks = 0; ks < 16; ks++) {
        uint32_t afr[4][4];
#pragma unroll
        for (int mt = 0; mt < 4; mt++) {
            int r = wm * 64 + mt * 16 + lr + lA_rhi * 8;
            int c = 2 * ks + lA_chi;
            ldsm4(afr[mt], sAb + (uint32_t)(r * 32 + (c ^ (r & 7))) * 16);
        }
        uint32_t bfr[2][4];
#pragma unroll
        for (int np = 0; np < 2; np++) {
            int r = wn * 32 + np * 16 + lr + lB_rhi * 8;
            int c = 2 * ks + lB_chi;
            ldsm4(bfr[np], sBb + (uint32_t)(r * 32 + (c ^ (r & 7))) * 16);
        }
#pragma unroll
        for (int mt = 0; mt < 4; mt++)
#pragma unroll
            for (int nt = 0; nt < 4; nt++)
                mma16816(acc[mt][nt], afr[mt], &bfr[nt >> 1][(nt & 1) * 2]);
    }

    // epilogue: bias + relu -> g_h1h fp16
    const int qr = lane >> 2, qc = (lane & 3) * 2;
#pragma unroll
    for (int mt = 0; mt < 4; mt++) {
#pragma unroll
        for (int half_ = 0; half_ < 2; half_++) {
            int row = rowBase + wm * 64 + mt * 16 + qr + half_ * 8;
            if (row < n) {
#pragma unroll
                for (int nt = 0; nt < 4; nt++) {
                    int col = wn * 32 + nt * 8 + qc;
                    float f0 = fmaxf(acc[mt][nt][half_ * 2]     + __ldg(bias + col),     0.f);
                    float f1 = fmaxf(acc[mt][nt][half_ * 2 + 1] + __ldg(bias + col + 1), 0.f);
                    __half2 h = __floats2half2_rn(f0, f1);
                    *(__half2*)(g_h1h + (size_t)row * 128 + col) = h;
                }
            }
        }
    }
}

// ---------------- GEMM2 (HMMA): [s|t] = h1 @ W2t^T ----------------
// block 128x80, K=128. 8 warps, one per 16 rows; 10 n-tiles of 8.
__global__ __launch_bounds__(256, 1) void k_gemm2_mma(const float* __restrict__ bias, int n) {
    extern __shared__ __align__(16) char smem[];   // A 32KB | B 20KB
    uint4* sA4 = (uint4*)smem;
    uint4* sB4 = (uint4*)(smem + 32768);
    const int tid = threadIdx.x;
    const int rowBase = blockIdx.x * 128;

    const uint4* a4 = (const uint4*)g_h1h;
    for (int i = tid; i < 2048; i += 256) {
        int r = i >> 4, c = i & 15;
        uint4 v = make_uint4(0u, 0u, 0u, 0u);
        int gr = rowBase + r;
        if (gr < n) v = a4[(size_t)gr * 16 + c];
        sA4[r * 16 + (c ^ (r & 7))] = v;
    }
    const uint4* b4 = (const uint4*)g_w2t;
    for (int i = tid; i < 1280; i += 256) {
        int r = i >> 4, c = i & 15;
        sB4[r * 16 + (c ^ (r & 7))] = b4[r * 16 + c];
    }
    __syncthreads();

    const int wid = tid >> 5, lane = tid & 31;
    const uint32_t sAb = smem_to_u32(sA4), sBb = smem_to_u32(sB4);

    float acc[10][4];
#pragma unroll
    for (int nt = 0; nt < 10; nt++)
#pragma unroll
        for (int j = 0; j < 4; j++) acc[nt][j] = 0.f;

    const int lr = lane & 7;
    const int lA_rhi = (lane >> 3) & 1, lA_chi = lane >> 4;
    const int lB_rhi = lane >> 4, lB_chi = (lane >> 3) & 1;

#pragma unroll 4
    for (int ks = 0; ks < 8; ks++) {
        uint32_t afr[4];
        {
            int r = wid * 16 + lr + lA_rhi * 8;
            int c = 2 * ks + lA_chi;
            ldsm4(afr, sAb + (uint32_t)(r * 16 + (c ^ (r & 7))) * 16);
        }
        uint32_t bfr[5][4];
#pragma unroll
        for (int np = 0; np < 5; np++) {
            int r = np * 16 + lr + lB_rhi * 8;
            int c = 2 * ks + lB_chi;
            ldsm4(bfr[np], sBb + (uint32_t)(r * 16 + (c ^ (r & 7))) * 16);
        }
#pragma unroll
        for (int nt = 0; nt < 10; nt++)
            mma16816(acc[nt], afr, &bfr[nt >> 1][(nt & 1) * 2]);
    }

    const int qr = lane >> 2, qc = (lane & 3) * 2;
#pragma unroll
    for (int half_ = 0; half_ < 2; half_++) {
        int row = rowBase + wid * 16 + qr + half_ * 8;
        if (row < n) {
#pragma unroll
            for (int nt = 0; nt < 5; nt++) {       // self -> g_s fp32 + bias
                int col = nt * 8 + qc;
                float2 v;
                v.x = acc[nt][half_ * 2]     + __ldg(bias + col);
                v.y = acc[nt][half_ * 2 + 1] + __ldg(bias + col + 1);
                *(float2*)(g_s + (size_t)row * 40 + col) = v;
            }
#pragma unroll
            for (int nt = 5; nt < 10; nt++) {      // neigh -> g_t fp16 (stride 64)
                int col = (nt - 5) * 8 + qc;
                __half2 h = __floats2half2_rn(acc[nt][half_ * 2], acc[nt][half_ * 2 + 1]);
                *(__half2*)(g_t + (size_t)row * 64 + col) = h;
            }
        }
    }
}

// ---------------- final: out = s + mean_agg(t) ----------------
__global__ void k_agg40(float* __restrict__ out, int n) {
    int w    = (blockIdx.x * blockDim.x + threadIdx.x) >> 5;
    int lane = threadIdx.x & 31;
    if (w >= n || lane >= 20) return;
    int b  = g_off[w];
    int e2 = g_off[w + 1];
    float2 acc = make_float2(0.f, 0.f);
    const __half2* __restrict__ base = (const __half2*)g_t;
#pragma unroll 4
    for (int i = b; i < e2; i++) {
        int s = g_csr[i];
        float2 f = __half22float2(base[(size_t)s * 32 + lane]);
        acc.x += f.x; acc.y += f.y;
    }
    float inv = 1.0f / (float)max(e2 - b, 1);
    float2 sv = ((const float2*)(g_s + (size_t)w * 40))[lane];
    float2 r = make_float2(sv.x + acc.x * inv, sv.y + acc.y * inv);
    ((float2*)(out + (size_t)w * 40))[lane] = r;
}

// ---------------- launch ----------------
extern "C" void kernel_launch(void* const* d_in, const int* in_sizes, int n_in,
                              void* d_out, int out_size) {
    const float* x   = (const float*)d_in[0];
    const int*   src = (const int*)  d_in[1];
    const int*   dst = (const int*)  d_in[2];
    const float* W1s = (const float*)d_in[3];
    const float* W1n = (const float*)d_in[4];
    const float* b1  = (const float*)d_in[5];
    const float* W2s = (const float*)d_in[6];
    const float* W2n = (const float*)d_in[7];
    const float* b2  = (const float*)d_in[8];
    float* out = (float*)d_out;

    const int E = in_sizes[1];
    const int N = in_sizes[0] / 128;
    const int nb = (N + 1023) / 1024;

    cudaFuncSetAttribute(k_gemm1_mma, cudaFuncAttributeMaxDynamicSharedMemorySize, 131072);
    cudaFuncSetAttribute(k_gemm2_mma, cudaFuncAttributeMaxDynamicSharedMemorySize, 53248);

    k_prep <<<(N * 64 + 255) / 256, 256>>>(x, N);
    k_prepw<<<(128 * 256 + 80 * 128 + 255) / 256, 256>>>(W1s, W1n, W2s, W2n);
    k_count<<<(E + 255) / 256, 256>>>(dst, E);
    k_scan1<<<nb, 1024>>>(N);
    k_scan2<<<1, 128>>>(nb, N);
    k_scan3<<<(N + 255) / 256, 256>>>(N);
    k_fill <<<(E + 255) / 256, 256>>>(src, dst, E);

    k_aggh     <<<(N + 7) / 8, 256>>>(N);
    k_gemm1_mma<<<(N + 127) / 128, 256, 131072>>>(b1, N);
    k_gemm2_mma<<<(N + 127) / 128, 256, 53248>>>(b2, N);
    k_agg40    <<<(N + 7) / 8, 256>>>(out, N);
}

// round 6
// speedup vs baseline: 1.7776x; 1.0768x over previous
#include <cuda_runtime.h>
#include <cuda_fp16.h>
#include <cstdint>

#define NNODES 100000
#define NEDGES 1600000

// ---------------- device scratch ----------------
__device__ int    g_deg[NNODES];
__device__ int    g_cur[NNODES];
__device__ int    g_off[NNODES + 1];
__device__ int    g_bsum[128];
__device__ int    g_csr[NEDGES];
__device__ __half g_a1[(size_t)NNODES * 256];   // [x fp16 (0..127) | agg fp16 (128..255)]
__device__ __half g_w1t[128 * 256];             // W1 concat, transposed: [n][k]
__device__ __half g_w2t[80 * 128];              // W2 concat, transposed: [n][k]
__device__ float  g_s [(size_t)NNODES * 40];    // h1 @ W2_self + b2
__device__ __half g_t [(size_t)NNODES * 64];    // h1 @ W2_neigh (fp16, stride 64)

// ---------------- baseline-PTX MMA helpers ----------------
__device__ __forceinline__ uint32_t smem_to_u32(const void* p) {
    uint32_t a;
    asm("{ .reg .u64 t; cvta.to.shared.u64 t, %1; cvt.u32.u64 %0, t; }" : "=r"(a) : "l"(p));
    return a;
}
__device__ __forceinline__ void ldsm4(uint32_t* r, uint32_t addr) {
    asm volatile("ldmatrix.sync.aligned.m8n8.x4.shared.b16 {%0,%1,%2,%3}, [%4];"
        : "=r"(r[0]), "=r"(r[1]), "=r"(r[2]), "=r"(r[3]) : "r"(addr));
}
__device__ __forceinline__ void mma16816(float* d, const uint32_t* a, const uint32_t* b) {
    asm volatile("mma.sync.aligned.m16n8k16.row.col.f32.f16.f16.f32 "
        "{%0,%1,%2,%3}, {%4,%5,%6,%7}, {%8,%9}, {%0,%1,%2,%3};"
        : "+f"(d[0]), "+f"(d[1]), "+f"(d[2]), "+f"(d[3])
        : "r"(a[0]), "r"(a[1]), "r"(a[2]), "r"(a[3]), "r"(b[0]), "r"(b[1]));
}

// ---------------- prep: zero deg + convert x to fp16 + transpose weights ----------------
__global__ void k_prep(const float* __restrict__ x,
                       const float* __restrict__ W1s, const float* __restrict__ W1n,
                       const float* __restrict__ W2s, const float* __restrict__ W2n, int n) {
    int i = blockIdx.x * blockDim.x + threadIdx.x;
    if (i < n) g_deg[i] = 0;
    if (i < n * 64) {
        int row = i >> 6, c2 = i & 63;
        float2 v = ((const float2*)x)[i];
        ((__half2*)g_a1)[(size_t)row * 128 + c2] = __float22half2_rn(v);
    }
    if (i < 128 * 256) {
        int nn = i >> 8, k = i & 255;
        float v = (k < 128) ? W1s[k * 128 + nn] : W1n[(k - 128) * 128 + nn];
        g_w1t[nn * 256 + k] = __float2half(v);
    } else if (i < 128 * 256 + 80 * 128) {
        int j = i - 128 * 256;
        int nn = j >> 7, k = j & 127;
        float v = (nn < 40) ? W2s[k * 40 + nn] : W2n[k * 40 + (nn - 40)];
        g_w2t[nn * 128 + k] = __float2half(v);
    }
}

// ---------------- CSR build ----------------
__global__ void k_count(const int* __restrict__ dst, int e) {
    int i = blockIdx.x * blockDim.x + threadIdx.x;
    if (i < e) atomicAdd(&g_deg[dst[i]], 1);
}

__global__ void k_scan1(int n) {
    __shared__ int sh[1024];
    int t = threadIdx.x;
    int i = blockIdx.x * 1024 + t;
    int v = (i < n) ? g_deg[i] : 0;
    sh[t] = v;
    __syncthreads();
#pragma unroll
    for (int o = 1; o < 1024; o <<= 1) {
        int x = (t >= o) ? sh[t - o] : 0;
        __syncthreads();
        sh[t] += x;
        __syncthreads();
    }
    if (i < n) g_off[i] = sh[t] - v;
    if (t == 1023) g_bsum[blockIdx.x] = sh[1023];
}

__global__ void k_scan2(int nb, int n) {
    __shared__ int sh[128];
    int t = threadIdx.x;
    int v = (t < nb) ? g_bsum[t] : 0;
    sh[t] = v;
    __syncthreads();
#pragma unroll
    for (int o = 1; o < 128; o <<= 1) {
        int x = (t >= o) ? sh[t - o] : 0;
        __syncthreads();
        sh[t] += x;
        __syncthreads();
    }
    g_bsum[t] = sh[t] - v;
    if (t == 127) g_off[n] = sh[127];
}

__global__ void k_scan3(int n) {
    int i = blockIdx.x * blockDim.x + threadIdx.x;
    if (i < n) { g_off[i] += g_bsum[i >> 10]; g_cur[i] = 0; }
}

__global__ void k_fill(const int* __restrict__ src, const int* __restrict__ dst, int e) {
    int i = blockIdx.x * blockDim.x + threadIdx.x;
    if (i < e) {
        int d = dst[i];
        int p = atomicAdd(&g_cur[d], 1);
        g_csr[g_off[d] + p] = src[i];
    }
}

// ---------------- mean aggregation: warp/node, 2 edges per iter, uint4 loads ----------------
__global__ void k_aggh(int n) {
    int w    = (blockIdx.x * blockDim.x + threadIdx.x) >> 5;
    int lane = threadIdx.x & 31;
    if (w >= n) return;
    int b  = g_off[w];
    int e2 = g_off[w + 1];
    const int half = lane >> 4;        // 0: even edges, 1: odd edges
    const int cl   = lane & 15;        // uint4 column (8 halves each)
    float2 a0 = make_float2(0.f, 0.f), a1 = make_float2(0.f, 0.f);
    float2 a2 = make_float2(0.f, 0.f), a3 = make_float2(0.f, 0.f);
    const uint4* __restrict__ base = (const uint4*)g_a1;   // row = 32 uint4; x-part = first 16
#pragma unroll 2
    for (int i = b + half; i < e2; i += 2) {
        int s = g_csr[i];
        uint4 raw = base[(size_t)s * 32 + cl];
        const __half2* h = (const __half2*)&raw;
        float2 f0 = __half22float2(h[0]), f1 = __half22float2(h[1]);
        float2 f2 = __half22float2(h[2]), f3 = __half22float2(h[3]);
        a0.x += f0.x; a0.y += f0.y; a1.x += f1.x; a1.y += f1.y;
        a2.x += f2.x; a2.y += f2.y; a3.x += f3.x; a3.y += f3.y;
    }
    a0.x += __shfl_xor_sync(0xffffffffu, a0.x, 16);
    a0.y += __shfl_xor_sync(0xffffffffu, a0.y, 16);
    a1.x += __shfl_xor_sync(0xffffffffu, a1.x, 16);
    a1.y += __shfl_xor_sync(0xffffffffu, a1.y, 16);
    a2.x += __shfl_xor_sync(0xffffffffu, a2.x, 16);
    a2.y += __shfl_xor_sync(0xffffffffu, a2.y, 16);
    a3.x += __shfl_xor_sync(0xffffffffu, a3.x, 16);
    a3.y += __shfl_xor_sync(0xffffffffu, a3.y, 16);
    if (half == 0) {
        float inv = 1.0f / (float)max(e2 - b, 1);
        __half2 h0 = __floats2half2_rn(a0.x * inv, a0.y * inv);
        __half2 h1 = __floats2half2_rn(a1.x * inv, a1.y * inv);
        __half2 h2 = __floats2half2_rn(a2.x * inv, a2.y * inv);
        __half2 h3 = __floats2half2_rn(a3.x * inv, a3.y * inv);
        uint4 o;
        o.x = *(uint32_t*)&h0; o.y = *(uint32_t*)&h1;
        o.z = *(uint32_t*)&h2; o.w = *(uint32_t*)&h3;
        ((uint4*)g_a1)[(size_t)w * 32 + 16 + cl] = o;   // agg-part
    }
}

// ---------------- fused GEMM (HMMA): h1 = relu([x|agg]@W1t^T + b1); [s|t] = h1@W2t^T ----------------
// block 128 rows. Phase 1: 8 warps 2x4, warp tile 64x32, K=256.
// Phase 2: h1 tile staged in smem fp16; warp w owns rows 16w..16w+15; N=80, K=128.
__global__ __launch_bounds__(256, 1) void k_gemm_fused(
    const float* __restrict__ bias1, const float* __restrict__ bias2, int n)
{
    extern __shared__ __align__(16) char smem[];   // [0,64K): A then W2; [64K,128K): W1 then h1
    uint4* sA4 = (uint4*)smem;
    uint4* sB4 = (uint4*)(smem + 65536);
    const int tid = threadIdx.x;
    const int rowBase = blockIdx.x * 128;

    // ---- fill A ([x|agg] tile, 128x256 halves) and B (W1t, 128x256) ----
    const uint4* a4 = (const uint4*)g_a1;
    for (int i = tid; i < 4096; i += 256) {
        int r = i >> 5, c = i & 31;
        uint4 v = make_uint4(0u, 0u, 0u, 0u);
        int gr = rowBase + r;
        if (gr < n) v = a4[(size_t)gr * 32 + c];
        sA4[r * 32 + (c ^ (r & 7))] = v;
    }
    const uint4* w14 = (const uint4*)g_w1t;
    for (int i = tid; i < 4096; i += 256) {
        int r = i >> 5, c = i & 31;
        sB4[r * 32 + (c ^ (r & 7))] = w14[r * 32 + c];
    }
    __syncthreads();

    const int wid = tid >> 5, lane = tid & 31;
    const int wm = wid >> 2, wn = wid & 3;
    const uint32_t sAb = smem_to_u32(sA4), sBb = smem_to_u32(sB4);

    float acc[4][4][4];
#pragma unroll
    for (int mt = 0; mt < 4; mt++)
#pragma unroll
        for (int nt = 0; nt < 4; nt++)
#pragma unroll
            for (int j = 0; j < 4; j++) acc[mt][nt][j] = 0.f;

    const int lr = lane & 7;
    const int lA_rhi = (lane >> 3) & 1, lA_chi = lane >> 4;
    const int lB_rhi = lane >> 4, lB_chi = (lane >> 3) & 1;

#pragma unroll 4
    for (int ks = 0; ks < 16; ks++) {
        uint32_t afr[4][4];
#pragma unroll
        for (int mt = 0; mt < 4; mt++) {
            int r = wm * 64 + mt * 16 + lr + lA_rhi * 8;
            int c = 2 * ks + lA_chi;
            ldsm4(afr[mt], sAb + (uint32_t)(r * 32 + (c ^ (r & 7))) * 16);
        }
        uint32_t bfr[2][4];
#pragma unroll
        for (int np = 0; np < 2; np++) {
            int r = wn * 32 + np * 16 + lr + lB_rhi * 8;
            int c = 2 * ks + lB_chi;
            ldsm4(bfr[np], sBb + (uint32_t)(r * 32 + (c ^ (r & 7))) * 16);
        }
#pragma unroll
        for (int mt = 0; mt < 4; mt++)
#pragma unroll
            for (int nt = 0; nt < 4; nt++)
                mma16816(acc[mt][nt], afr[mt], &bfr[nt >> 1][(nt & 1) * 2]);
    }
    __syncthreads();   // all ldsm reads of sA (A) and sB (W1) complete

    // ---- load W2 (80x128 halves) into sA region ----
    const uint4* w24 = (const uint4*)g_w2t;
    for (int i = tid; i < 1280; i += 256) {
        int r = i >> 4, c = i & 15;
        sA4[r * 16 + (c ^ (r & 7))] = w24[r * 16 + c];
    }

    // ---- epilogue 1: bias+relu -> h1 fp16 into sB region (128x128, 16 uint4/row swizzled) ----
    __half2* sH2 = (__half2*)sB4;
    const int qr = lane >> 2, qc = (lane & 3) * 2;
#pragma unroll
    for (int mt = 0; mt < 4; mt++) {
#pragma unroll
        for (int half_ = 0; half_ < 2; half_++) {
            int lrow = wm * 64 + mt * 16 + qr + half_ * 8;
#pragma unroll
            for (int nt = 0; nt < 4; nt++) {
                int col = wn * 32 + nt * 8 + qc;
                float f0 = fmaxf(acc[mt][nt][half_ * 2]     + __ldg(bias1 + col),     0.f);
                float f1 = fmaxf(acc[mt][nt][half_ * 2 + 1] + __ldg(bias1 + col + 1), 0.f);
                int cu = col >> 3;
                int h2idx = (lrow * 16 + (cu ^ (lrow & 7))) * 4 + ((col & 7) >> 1);
                sH2[h2idx] = __floats2half2_rn(f0, f1);
            }
        }
    }
    __syncthreads();

    // ---- phase 2: [s|t] = h1 @ W2t^T, warp wid -> rows wid*16..+16 ----
    float acc2[10][4];
#pragma unroll
    for (int nt = 0; nt < 10; nt++)
#pragma unroll
        for (int j = 0; j < 4; j++) acc2[nt][j] = 0.f;

#pragma unroll 4
    for (int ks = 0; ks < 8; ks++) {
        uint32_t afr[4];
        {
            int r = wid * 16 + lr + lA_rhi * 8;
            int c = 2 * ks + lA_chi;
            ldsm4(afr, sBb + (uint32_t)(r * 16 + (c ^ (r & 7))) * 16);
        }
        uint32_t bfr[5][4];
#pragma unroll
        for (int np = 0; np < 5; np++) {
            int r = np * 16 + lr + lB_rhi * 8;
            int c = 2 * ks + lB_chi;
            ldsm4(bfr[np], sAb + (uint32_t)(r * 16 + (c ^ (r & 7))) * 16);
        }
#pragma unroll
        for (int nt = 0; nt < 10; nt++)
            mma16816(acc2[nt], afr, &bfr[nt >> 1][(nt & 1) * 2]);
    }

    // ---- epilogue 2 ----
#pragma unroll
    for (int half_ = 0; half_ < 2; half_++) {
        int row = rowBase + wid * 16 + qr + half_ * 8;
        if (row < n) {
#pragma unroll
            for (int nt = 0; nt < 5; nt++) {       // self -> g_s fp32 + bias2
                int col = nt * 8 + qc;
                float2 v;
                v.x = acc2[nt][half_ * 2]     + __ldg(bias2 + col);
                v.y = acc2[nt][half_ * 2 + 1] + __ldg(bias2 + col + 1);
                *(float2*)(g_s + (size_t)row * 40 + col) = v;
            }
#pragma unroll
            for (int nt = 5; nt < 10; nt++) {      // neigh -> g_t fp16 (stride 64)
                int col = (nt - 5) * 8 + qc;
                __half2 h = __floats2half2_rn(acc2[nt][half_ * 2], acc2[nt][half_ * 2 + 1]);
                *(__half2*)(g_t + (size_t)row * 64 + col) = h;
            }
        }
    }
}

// ---------------- final: out = s + mean_agg(t) ----------------
__global__ void k_agg40(float* __restrict__ out, int n) {
    int w    = (blockIdx.x * blockDim.x + threadIdx.x) >> 5;
    int lane = threadIdx.x & 31;
    if (w >= n || lane >= 20) return;
    int b  = g_off[w];
    int e2 = g_off[w + 1];
    float2 acc = make_float2(0.f, 0.f);
    const __half2* __restrict__ base = (const __half2*)g_t;
#pragma unroll 4
    for (int i = b; i < e2; i++) {
        int s = g_csr[i];
        float2 f = __half22float2(base[(size_t)s * 32 + lane]);
        acc.x += f.x; acc.y += f.y;
    }
    float inv = 1.0f / (float)max(e2 - b, 1);
    float2 sv = ((const float2*)(g_s + (size_t)w * 40))[lane];
    float2 r = make_float2(sv.x + acc.x * inv, sv.y + acc.y * inv);
    ((float2*)(out + (size_t)w * 40))[lane] = r;
}

// ---------------- launch ----------------
extern "C" void kernel_launch(void* const* d_in, const int* in_sizes, int n_in,
                              void* d_out, int out_size) {
    const float* x   = (const float*)d_in[0];
    const int*   src = (const int*)  d_in[1];
    const int*   dst = (const int*)  d_in[2];
    const float* W1s = (const float*)d_in[3];
    const float* W1n = (const float*)d_in[4];
    const float* b1  = (const float*)d_in[5];
    const float* W2s = (const float*)d_in[6];
    const float* W2n = (const float*)d_in[7];
    const float* b2  = (const float*)d_in[8];
    float* out = (float*)d_out;

    const int E = in_sizes[1];
    const int N = in_sizes[0] / 128;
    const int nb = (N + 1023) / 1024;

    cudaFuncSetAttribute(k_gemm_fused, cudaFuncAttributeMaxDynamicSharedMemorySize, 131072);

    k_prep <<<(N * 64 + 255) / 256, 256>>>(x, W1s, W1n, W2s, W2n, N);
    k_count<<<(E + 255) / 256, 256>>>(dst, E);
    k_scan1<<<nb, 1024>>>(N);
    k_scan2<<<1, 128>>>(nb, N);
    k_scan3<<<(N + 255) / 256, 256>>>(N);
    k_fill <<<(E + 255) / 256, 256>>>(src, dst, E);

    k_aggh      <<<(N + 7) / 8, 256>>>(N);
    k_gemm_fused<<<(N + 127) / 128, 256, 131072>>>(b1, b2, N);
    k_agg40     <<<(N + 7) / 8, 256>>>(out, N);
}

// round 7
// speedup vs baseline: 1.8053x; 1.0156x over previous
#include <cuda_runtime.h>
#include <cuda_fp16.h>
#include <cstdint>

#define NNODES 100000
#define NEDGES 1600000

// ---------------- device scratch (zero-initialized at load; re-zeroed by k_agg40) ----------------
__device__ int    g_deg[NNODES];        // must be 0 on entry to each kernel_launch
__device__ int    g_cur[NNODES];        // must be 0 on entry
__device__ int    g_off[NNODES + 1];    // per-block-local exclusive scan (add g_bsum lazily)
__device__ int    g_bsum[128];
__device__ int    g_csr[NEDGES];
__device__ __half g_a1[(size_t)NNODES * 256];   // [x fp16 (0..127) | agg fp16 (128..255)]
__device__ __half g_w1t[128 * 256];             // W1 concat, transposed: [n][k]
__device__ __half g_w2t[80 * 128];              // W2 concat, transposed: [n][k]
__device__ float  g_s [(size_t)NNODES * 40];    // h1 @ W2_self + b2
__device__ __half g_t [(size_t)NNODES * 64];    // h1 @ W2_neigh (fp16, stride 64)

// ---------------- baseline-PTX MMA helpers ----------------
__device__ __forceinline__ uint32_t smem_to_u32(const void* p) {
    uint32_t a;
    asm("{ .reg .u64 t; cvta.to.shared.u64 t, %1; cvt.u32.u64 %0, t; }" : "=r"(a) : "l"(p));
    return a;
}
__device__ __forceinline__ void ldsm4(uint32_t* r, uint32_t addr) {
    asm volatile("ldmatrix.sync.aligned.m8n8.x4.shared.b16 {%0,%1,%2,%3}, [%4];"
        : "=r"(r[0]), "=r"(r[1]), "=r"(r[2]), "=r"(r[3]) : "r"(addr));
}
__device__ __forceinline__ void mma16816(float* d, const uint32_t* a, const uint32_t* b) {
    asm volatile("mma.sync.aligned.m16n8k16.row.col.f32.f16.f16.f32 "
        "{%0,%1,%2,%3}, {%4,%5,%6,%7}, {%8,%9}, {%0,%1,%2,%3};"
        : "+f"(d[0]), "+f"(d[1]), "+f"(d[2]), "+f"(d[3])
        : "r"(a[0]), "r"(a[1]), "r"(a[2]), "r"(a[3]), "r"(b[0]), "r"(b[1]));
}

// ---------------- fused prep + degree count ----------------
// g_deg is pre-zeroed (module load / previous k_agg40), so count can run immediately.
__global__ void k_prep_count(const float* __restrict__ x,
                             const float* __restrict__ W1s, const float* __restrict__ W1n,
                             const float* __restrict__ W2s, const float* __restrict__ W2n,
                             const int* __restrict__ dst, int n, int e) {
    int i = blockIdx.x * blockDim.x + threadIdx.x;
    if (i < e) atomicAdd(&g_deg[dst[i]], 1);
    if (i < n * 64) {
        int row = i >> 6, c2 = i & 63;
        float2 v = ((const float2*)x)[i];
        ((__half2*)g_a1)[(size_t)row * 128 + c2] = __float22half2_rn(v);
    }
    if (i < 128 * 256) {
        int nn = i >> 8, k = i & 255;
        float v = (k < 128) ? W1s[k * 128 + nn] : W1n[(k - 128) * 128 + nn];
        g_w1t[nn * 256 + k] = __float2half(v);
    } else if (i < 128 * 256 + 80 * 128) {
        int j = i - 128 * 256;
        int nn = j >> 7, k = j & 127;
        float v = (nn < 40) ? W2s[k * 40 + nn] : W2n[k * 40 + (nn - 40)];
        g_w2t[nn * 128 + k] = __float2half(v);
    }
}

// ---------------- two-level scan (block-local; bsum applied lazily by consumers) ----------------
__global__ void k_scan1(int n) {
    __shared__ int sh[1024];
    int t = threadIdx.x;
    int i = blockIdx.x * 1024 + t;
    int v = (i < n) ? g_deg[i] : 0;
    sh[t] = v;
    __syncthreads();
#pragma unroll
    for (int o = 1; o < 1024; o <<= 1) {
        int x = (t >= o) ? sh[t - o] : 0;
        __syncthreads();
        sh[t] += x;
        __syncthreads();
    }
    if (i < n) g_off[i] = sh[t] - v;   // exclusive, block-local
    if (t == 1023) g_bsum[blockIdx.x] = sh[1023];
}

__global__ void k_scan2(int nb, int n) {
    __shared__ int sh[128];
    int t = threadIdx.x;
    int v = (t < nb) ? g_bsum[t] : 0;
    sh[t] = v;
    __syncthreads();
#pragma unroll
    for (int o = 1; o < 128; o <<= 1) {
        int x = (t >= o) ? sh[t - o] : 0;
        __syncthreads();
        sh[t] += x;
        __syncthreads();
    }
    g_bsum[t] = sh[t] - v;             // exclusive block offsets
    // sentinel: g_off[n] + g_bsum[n>>10] must equal E
    if (t == (n >> 10)) g_off[n] = sh[127] - (sh[t] - v);
}

__global__ void k_fill(const int* __restrict__ src, const int* __restrict__ dst, int e) {
    int i = blockIdx.x * blockDim.x + threadIdx.x;
    if (i < e) {
        int d = dst[i];
        int p = atomicAdd(&g_cur[d], 1);
        g_csr[g_off[d] + g_bsum[d >> 10] + p] = src[i];
    }
}

// ---------------- mean aggregation: warp/node, 2 edges per iter, uint4 loads ----------------
__global__ void k_aggh(int n) {
    int w    = (blockIdx.x * blockDim.x + threadIdx.x) >> 5;
    int lane = threadIdx.x & 31;
    if (w >= n) return;
    int b  = g_off[w]     + g_bsum[w >> 10];
    int e2 = g_off[w + 1] + g_bsum[(w + 1) >> 10];
    const int half = lane >> 4;        // 0: even edges, 1: odd edges
    const int cl   = lane & 15;        // uint4 column (8 halves each)
    float2 a0 = make_float2(0.f, 0.f), a1 = make_float2(0.f, 0.f);
    float2 a2 = make_float2(0.f, 0.f), a3 = make_float2(0.f, 0.f);
    const uint4* __restrict__ base = (const uint4*)g_a1;   // row = 32 uint4; x-part = first 16
#pragma unroll 4
    for (int i = b + half; i < e2; i += 2) {
        int s = g_csr[i];
        uint4 raw = base[(size_t)s * 32 + cl];
        const __half2* h = (const __half2*)&raw;
        float2 f0 = __half22float2(h[0]), f1 = __half22float2(h[1]);
        float2 f2 = __half22float2(h[2]), f3 = __half22float2(h[3]);
        a0.x += f0.x; a0.y += f0.y; a1.x += f1.x; a1.y += f1.y;
        a2.x += f2.x; a2.y += f2.y; a3.x += f3.x; a3.y += f3.y;
    }
    a0.x += __shfl_xor_sync(0xffffffffu, a0.x, 16);
    a0.y += __shfl_xor_sync(0xffffffffu, a0.y, 16);
    a1.x += __shfl_xor_sync(0xffffffffu, a1.x, 16);
    a1.y += __shfl_xor_sync(0xffffffffu, a1.y, 16);
    a2.x += __shfl_xor_sync(0xffffffffu, a2.x, 16);
    a2.y += __shfl_xor_sync(0xffffffffu, a2.y, 16);
    a3.x += __shfl_xor_sync(0xffffffffu, a3.x, 16);
    a3.y += __shfl_xor_sync(0xffffffffu, a3.y, 16);
    if (half == 0) {
        float inv = 1.0f / (float)max(e2 - b, 1);
        __half2 h0 = __floats2half2_rn(a0.x * inv, a0.y * inv);
        __half2 h1 = __floats2half2_rn(a1.x * inv, a1.y * inv);
        __half2 h2 = __floats2half2_rn(a2.x * inv, a2.y * inv);
        __half2 h3 = __floats2half2_rn(a3.x * inv, a3.y * inv);
        uint4 o;
        o.x = *(uint32_t*)&h0; o.y = *(uint32_t*)&h1;
        o.z = *(uint32_t*)&h2; o.w = *(uint32_t*)&h3;
        ((uint4*)g_a1)[(size_t)w * 32 + 16 + cl] = o;   // agg-part
    }
}

// ---------------- fused GEMM (HMMA): h1 = relu([x|agg]@W1t^T + b1); [s|t] = h1@W2t^T ----------------
__global__ __launch_bounds__(256, 1) void k_gemm_fused(
    const float* __restrict__ bias1, const float* __restrict__ bias2, int n)
{
    extern __shared__ __align__(16) char smem[];   // [0,64K): A then W2; [64K,128K): W1 then h1
    uint4* sA4 = (uint4*)smem;
    uint4* sB4 = (uint4*)(smem + 65536);
    const int tid = threadIdx.x;
    const int rowBase = blockIdx.x * 128;

    const uint4* a4 = (const uint4*)g_a1;
    for (int i = tid; i < 4096; i += 256) {
        int r = i >> 5, c = i & 31;
        uint4 v = make_uint4(0u, 0u, 0u, 0u);
        int gr = rowBase + r;
        if (gr < n) v = a4[(size_t)gr * 32 + c];
        sA4[r * 32 + (c ^ (r & 7))] = v;
    }
    const uint4* w14 = (const uint4*)g_w1t;
    for (int i = tid; i < 4096; i += 256) {
        int r = i >> 5, c = i & 31;
        sB4[r * 32 + (c ^ (r & 7))] = w14[r * 32 + c];
    }
    __syncthreads();

    const int wid = tid >> 5, lane = tid & 31;
    const int wm = wid >> 2, wn = wid & 3;
    const uint32_t sAb = smem_to_u32(sA4), sBb = smem_to_u32(sB4);

    float acc[4][4][4];
#pragma unroll
    for (int mt = 0; mt < 4; mt++)
#pragma unroll
        for (int nt = 0; nt < 4; nt++)
#pragma unroll
            for (int j = 0; j < 4; j++) acc[mt][nt][j] = 0.f;

    const int lr = lane & 7;
    const int lA_rhi = (lane >> 3) & 1, lA_chi = lane >> 4;
    const int lB_rhi = lane >> 4, lB_chi = (lane >> 3) & 1;

#pragma unroll 4
    for (int ks = 0; ks < 16; ks++) {
        uint32_t afr[4][4];
#pragma unroll
        for (int mt = 0; mt < 4; mt++) {
            int r = wm * 64 + mt * 16 + lr + lA_rhi * 8;
            int c = 2 * ks + lA_chi;
            ldsm4(afr[mt], sAb + (uint32_t)(r * 32 + (c ^ (r & 7))) * 16);
        }
        uint32_t bfr[2][4];
#pragma unroll
        for (int np = 0; np < 2; np++) {
            int r = wn * 32 + np * 16 + lr + lB_rhi * 8;
            int c = 2 * ks + lB_chi;
            ldsm4(bfr[np], sBb + (uint32_t)(r * 32 + (c ^ (r & 7))) * 16);
        }
#pragma unroll
        for (int mt = 0; mt < 4; mt++)
#pragma unroll
            for (int nt = 0; nt < 4; nt++)
                mma16816(acc[mt][nt], afr[mt], &bfr[nt >> 1][(nt & 1) * 2]);
    }
    __syncthreads();

    const uint4* w24 = (const uint4*)g_w2t;
    for (int i = tid; i < 1280; i += 256) {
        int r = i >> 4, c = i & 15;
        sA4[r * 16 + (c ^ (r & 7))] = w24[r * 16 + c];
    }

    __half2* sH2 = (__half2*)sB4;
    const int qr = lane >> 2, qc = (lane & 3) * 2;
#pragma unroll
    for (int mt = 0; mt < 4; mt++) {
#pragma unroll
        for (int half_ = 0; half_ < 2; half_++) {
            int lrow = wm * 64 + mt * 16 + qr + half_ * 8;
#pragma unroll
            for (int nt = 0; nt < 4; nt++) {
                int col = wn * 32 + nt * 8 + qc;
                float f0 = fmaxf(acc[mt][nt][half_ * 2]     + __ldg(bias1 + col),     0.f);
                float f1 = fmaxf(acc[mt][nt][half_ * 2 + 1] + __ldg(bias1 + col + 1), 0.f);
                int cu = col >> 3;
                int h2idx = (lrow * 16 + (cu ^ (lrow & 7))) * 4 + ((col & 7) >> 1);
                sH2[h2idx] = __floats2half2_rn(f0, f1);
            }
        }
    }
    __syncthreads();

    float acc2[10][4];
#pragma unroll
    for (int nt = 0; nt < 10; nt++)
#pragma unroll
        for (int j = 0; j < 4; j++) acc2[nt][j] = 0.f;

#pragma unroll 4
    for (int ks = 0; ks < 8; ks++) {
        uint32_t afr[4];
        {
            int r = wid * 16 + lr + lA_rhi * 8;
            int c = 2 * ks + lA_chi;
            ldsm4(afr, sBb + (uint32_t)(r * 16 + (c ^ (r & 7))) * 16);
        }
        uint32_t bfr[5][4];
#pragma unroll
        for (int np = 0; np < 5; np++) {
            int r = np * 16 + lr + lB_rhi * 8;
            int c = 2 * ks + lB_chi;
            ldsm4(bfr[np], sAb + (uint32_t)(r * 16 + (c ^ (r & 7))) * 16);
        }
#pragma unroll
        for (int nt = 0; nt < 10; nt++)
            mma16816(acc2[nt], afr, &bfr[nt >> 1][(nt & 1) * 2]);
    }

#pragma unroll
    for (int half_ = 0; half_ < 2; half_++) {
        int row = rowBase + wid * 16 + qr + half_ * 8;
        if (row < n) {
#pragma unroll
            for (int nt = 0; nt < 5; nt++) {
                int col = nt * 8 + qc;
                float2 v;
                v.x = acc2[nt][half_ * 2]     + __ldg(bias2 + col);
                v.y = acc2[nt][half_ * 2 + 1] + __ldg(bias2 + col + 1);
                *(float2*)(g_s + (size_t)row * 40 + col) = v;
            }
#pragma unroll
            for (int nt = 5; nt < 10; nt++) {
                int col = (nt - 5) * 8 + qc;
                __half2 h = __floats2half2_rn(acc2[nt][half_ * 2], acc2[nt][half_ * 2 + 1]);
                *(__half2*)(g_t + (size_t)row * 64 + col) = h;
            }
        }
    }
}

// ---------------- final: out = s + mean_agg(t); re-zero deg/cur for next invocation ----------------
__global__ void k_agg40(float* __restrict__ out, int n) {
    int w    = (blockIdx.x * blockDim.x + threadIdx.x) >> 5;
    int lane = threadIdx.x & 31;
    if (w >= n) return;
    if (lane == 20) g_deg[w] = 0;
    if (lane == 21) g_cur[w] = 0;
    if (lane >= 20) return;
    int b  = g_off[w]     + g_bsum[w >> 10];
    int e2 = g_off[w + 1] + g_bsum[(w + 1) >> 10];
    float2 acc = make_float2(0.f, 0.f);
    const __half2* __restrict__ base = (const __half2*)g_t;
#pragma unroll 4
    for (int i = b; i < e2; i++) {
        int s = g_csr[i];
        float2 f = __half22float2(base[(size_t)s * 32 + lane]);
        acc.x += f.x; acc.y += f.y;
    }
    float inv = 1.0f / (float)max(e2 - b, 1);
    float2 sv = ((const float2*)(g_s + (size_t)w * 40))[lane];
    float2 r = make_float2(sv.x + acc.x * inv, sv.y + acc.y * inv);
    ((float2*)(out + (size_t)w * 40))[lane] = r;
}

// ---------------- launch ----------------
extern "C" void kernel_launch(void* const* d_in, const int* in_sizes, int n_in,
                              void* d_out, int out_size) {
    const float* x   = (const float*)d_in[0];
    const int*   src = (const int*)  d_in[1];
    const int*   dst = (const int*)  d_in[2];
    const float* W1s = (const float*)d_in[3];
    const float* W1n = (const float*)d_in[4];
    const float* b1  = (const float*)d_in[5];
    const float* W2s = (const float*)d_in[6];
    const float* W2n = (const float*)d_in[7];
    const float* b2  = (const float*)d_in[8];
    float* out = (float*)d_out;

    const int E = in_sizes[1];
    const int N = in_sizes[0] / 128;
    const int nb = (N + 1023) / 1024;

    cudaFuncSetAttribute(k_gemm_fused, cudaFuncAttributeMaxDynamicSharedMemorySize, 131072);

    k_prep_count<<<(N * 64 + 255) / 256, 256>>>(x, W1s, W1n, W2s, W2n, dst, N, E);
    k_scan1<<<nb, 1024>>>(N);
    k_scan2<<<1, 128>>>(nb, N);
    k_fill <<<(E + 255) / 256, 256>>>(src, dst, E);

    k_aggh      <<<(N + 7) / 8, 256>>>(N);
    k_gemm_fused<<<(N + 127) / 128, 256, 131072>>>(b1, b2, N);
    k_agg40     <<<(N + 7) / 8, 256>>>(out, N);
}